// round 7
// baseline (speedup 1.0000x reference)
#include <cuda_runtime.h>

#define KF_B 2048
#define KF_T 512
#define KF_D 8
#define KF_M 2

// Output layout (float offsets): means, covs, Rs, Hs concatenated.
#define OFF_MEANS 0
#define OFF_COVS  (KF_B * KF_T * KF_D)                       // 8388608
#define OFF_RS    (OFF_COVS + KF_B * KF_T * KF_D * KF_D)     // 75497472
#define OFF_HS    (OFF_RS + KF_B * KF_T * KF_M * KF_M)       // 79691776

#define SCAN_BLOCKS (KF_B / 4)   // 512 blocks: 4 chains/warp = 2 lane-groups x 2 reg-streams
#define FILL_BLOCKS 256

typedef unsigned long long ull;

__device__ __forceinline__ ull ff_pack2(float lo, float hi) {
    ull r;
    asm("mov.b64 %0, {%1, %2};" : "=l"(r) : "f"(lo), "f"(hi));
    return r;
}
__device__ __forceinline__ ull ff_dup(float v) { return ff_pack2(v, v); }
__device__ __forceinline__ ull ff_fma2(ull a, ull b, ull c) {
    ull r;
    asm("fma.rn.f32x2 %0, %1, %2, %3;" : "=l"(r) : "l"(a), "l"(b), "l"(c));
    return r;
}
__device__ __forceinline__ ull ff_add2(ull a, ull b) {
    ull r;
    asm("add.rn.f32x2 %0, %1, %2;" : "=l"(r) : "l"(a), "l"(b));
    return r;
}
__device__ __forceinline__ float2 ff_unpack(ull v) {
    float2 r;
    asm("mov.b64 {%0, %1}, %2;" : "=f"(r.x), "=f"(r.y) : "l"(v));
    return r;
}
__device__ __forceinline__ ull shflx8_64(ull v) {
    float2 p = ff_unpack(v);
    p.x = __shfl_xor_sync(0xffffffffu, p.x, 8);
    p.y = __shfl_xor_sync(0xffffffffu, p.y, 8);
    return ff_pack2(p.x, p.y);
}

__global__ void __launch_bounds__(32) kf_kernel(
    const float* __restrict__ xin_g,   // [B,T,M]
    const float* __restrict__ mean0,   // [B,D]
    const float* __restrict__ cov0,    // [B,D,D]
    const float* __restrict__ Fg,      // [D,D]
    const float* __restrict__ Hg,      // [M,D]
    const float* __restrict__ Qg,      // [D,D]
    const float* __restrict__ Rg,      // [M,M]
    float* __restrict__ out)
{
    // ---------------- broadcast-fill blocks (Rs, Hs) ----------------
    if (blockIdx.x >= SCAN_BLOCKS) {
        const size_t BT = (size_t)KF_B * KF_T;
        float4 r4 = *(const float4*)Rg;
        float4 h0v = *(const float4*)(Hg + 0);
        float4 h1v = *(const float4*)(Hg + 4);
        float4 h2v = *(const float4*)(Hg + 8);
        float4 h3v = *(const float4*)(Hg + 12);
        float4* Rs = (float4*)(out + OFF_RS);
        float4* Hs = (float4*)(out + OFF_HS);
        const size_t nthr = (size_t)FILL_BLOCKS * 32;
        const size_t tid  = (size_t)(blockIdx.x - SCAN_BLOCKS) * 32 + threadIdx.x;
        for (size_t i = tid; i < BT; i += nthr)
            Rs[i] = r4;
        for (size_t i = tid; i < BT; i += nthr) {
            float4* p = Hs + i * 4;
            p[0] = h0v; p[1] = h1v; p[2] = h2v; p[3] = h3v;
        }
        return;
    }

    // ---------------- scan: 4 chains/warp = 2 lane-chains x 2 reg-streams ----------------
    // lane = g*16 + h*8 + e ; stream s in {0,1} handles chain b = blockIdx.x*4 + s*2 + g
    const int lane = threadIdx.x & 31;
    const int g    = lane >> 4;
    const int sub  = lane & 15;
    const int e    = sub & 7;
    const int h    = sub >> 3;
    const bool h0  = (h == 0);
    const int j0   = 4 * h;

    // ---- loop-invariant registers (SHARED by both streams: same lane roles) ----
    float H0h[4], H1h[4];              // H[m][j0+i]
#pragma unroll
    for (int i = 0; i < 4; ++i) { H0h[i] = Hg[j0 + i]; H1h[i] = Hg[8 + j0 + i]; }

    float Frh[4];                      // F[e][j0+i]
#pragma unroll
    for (int i = 0; i < 4; ++i) Frh[i] = Fg[e * 8 + j0 + i];

    // Fd[k] = dup(F[e][k]) — hoisted cov_p scalars
    ull Fd[8];
#pragma unroll
    for (int k = 0; k < 8; ++k) Fd[k] = ff_dup(Fg[e * 8 + k]);

    // HF[m][j] for j in this half (hm carried via mean_u)
    float HF0h[4], HF1h[4];
#pragma unroll
    for (int i = 0; i < 4; ++i) {
        const int j = j0 + i;
        float a0 = 0.f, a1 = 0.f;
#pragma unroll
        for (int k = 0; k < 8; ++k) {
            a0 = fmaf(Hg[k],     Fg[k * 8 + j], a0);
            a1 = fmaf(Hg[8 + k], Fg[k * 8 + j], a1);
        }
        HF0h[i] = a0; HF1h[i] = a1;
    }

    // Fpk[kk][p] = (F[2p][j0+kk], F[2p+1][j0+kk]) — T1 partial operands
    ull Fpk[4][4];
#pragma unroll
    for (int kk = 0; kk < 4; ++kk)
#pragma unroll
        for (int p = 0; p < 4; ++p)
            Fpk[kk][p] = ff_pack2(Fg[(2 * p) * 8 + j0 + kk], Fg[(2 * p + 1) * 8 + j0 + kk]);

    const ull Qp0 = ff_pack2(Qg[e * 8 + j0],     Qg[e * 8 + j0 + 1]);
    const ull Qp1 = ff_pack2(Qg[e * 8 + j0 + 2], Qg[e * 8 + j0 + 3]);

    const float r00 = Rg[0], r01 = Rg[1], r11 = Rg[3];

    // ---- per-stream state ----
    float cov[2][4];
    float mean_e[2];
    float hm0[2], hm1[2];
    float2 x[2];
    const float* xrow[2];
    float* outM[2];
    float* outC[2];

#pragma unroll
    for (int s = 0; s < 2; ++s) {
        const int b = blockIdx.x * 4 + s * 2 + g;
        float4 c = *(const float4*)(cov0 + b * 64 + e * 8 + j0);
        cov[s][0]=c.x; cov[s][1]=c.y; cov[s][2]=c.z; cov[s][3]=c.w;
        mean_e[s] = mean0[b * 8 + e];
        float4 a = *(const float4*)(mean0 + b * 8);
        float4 d = *(const float4*)(mean0 + b * 8 + 4);
        float m[8] = {a.x,a.y,a.z,a.w,d.x,d.y,d.z,d.w};
        float s0 = 0.f, s1 = 0.f;
#pragma unroll
        for (int j = 0; j < 8; ++j) {
            s0 = fmaf(Hg[j],     m[j], s0);
            s1 = fmaf(Hg[8 + j], m[j], s1);
        }
        hm0[s] = s0; hm1[s] = s1;
        outM[s] = out + OFF_MEANS + (size_t)b * (KF_T * KF_D);
        outC[s] = out + OFF_COVS  + (size_t)b * (KF_T * KF_D * KF_D);
        xrow[s] = xin_g + (size_t)b * (KF_T * KF_M);
        x[s] = *(const float2*)xrow[s];
    }

    // SMEM: per-stream regions, per-chain sub-layout as in R4 (conflict-free)
    __shared__ __align__(16) float sHP[2][2 * 16];
    __shared__ __align__(16) float sMu[2][2 * 8];
    __shared__ __align__(16) float sT1[2][2 * 72];

    // Per-stream mid-phase temporaries carried between phase loops
    float hpA[2], hpB[2];              // hp0, hp1 (this e, combined)
    float Aa[2][4], Bb[2][4];
    float Kt0[2], Kt1[2];
    float2 xn[2];

#pragma unroll 1
    for (int t = 0; t < KF_T; ++t) {
        const int tn = (t + 1 < KF_T) ? t + 1 : t;

        // ================= PHASE 1 (both streams) =================
#pragma unroll
        for (int s = 0; s < 2; ++s) {
            if (h0) outM[s][t * 8 + e] = mean_e[s];
            *(float4*)(outC[s] + t * 64 + e * 8 + j0) =
                make_float4(cov[s][0], cov[s][1], cov[s][2], cov[s][3]);
            xn[s] = *(const float2*)(xrow[s] + tn * 2);

            float hp0 = 0.f, hp1 = 0.f;
#pragma unroll
            for (int i = 0; i < 4; ++i) {
                hp0 = fmaf(H0h[i], cov[s][i], hp0);
                hp1 = fmaf(H1h[i], cov[s][i], hp1);
            }
            hp0 += __shfl_xor_sync(0xffffffffu, hp0, 8);
            hp1 += __shfl_xor_sync(0xffffffffu, hp1, 8);
            hpA[s] = hp0; hpB[s] = hp1;
            if (h0) { sHP[s][g * 16 + e] = hp0; sHP[s][g * 16 + 8 + e] = hp1; }
        }
        __syncwarp();

        // ================= PHASE 2 (both streams) =================
#pragma unroll
        for (int s = 0; s < 2; ++s) {
            const float4 Ah = *(const float4*)&sHP[s][g * 16 + j0];
            const float4 Bh = *(const float4*)&sHP[s][g * 16 + 8 + j0];
            Aa[s][0]=Ah.x; Aa[s][1]=Ah.y; Aa[s][2]=Ah.z; Aa[s][3]=Ah.w;
            Bb[s][0]=Bh.x; Bb[s][1]=Bh.y; Bb[s][2]=Bh.z; Bb[s][3]=Bh.w;

            float S00 = 0.f, S01 = 0.f, S11 = 0.f;
#pragma unroll
            for (int i = 0; i < 4; ++i) {
                S00 = fmaf(H0h[i], Aa[s][i], S00);
                S01 = fmaf(H1h[i], Aa[s][i], S01);
                S11 = fmaf(H1h[i], Bb[s][i], S11);
            }
            S00 = r00 + S00 + __shfl_xor_sync(0xffffffffu, S00, 8);
            S01 = r01 + S01 + __shfl_xor_sync(0xffffffffu, S01, 8);
            S11 = r11 + S11 + __shfl_xor_sync(0xffffffffu, S11, 8);

            const float idet = __fdividef(1.0f, fmaf(S00, S11, -S01 * S01));
            Kt0[s] = (S11 * hpA[s] - S01 * hpB[s]) * idet;
            Kt1[s] = (S00 * hpB[s] - S01 * hpA[s]) * idet;
            const float rs0 = x[s].x - hm0[s];
            const float rs1 = x[s].y - hm1[s];
            const float mu  = fmaf(Kt0[s], rs0, fmaf(Kt1[s], rs1, mean_e[s]));
            if (h0) sMu[s][g * 8 + e] = mu;

            // cov_u half-row
            float cu[4];
#pragma unroll
            for (int i = 0; i < 4; ++i)
                cu[i] = cov[s][i] - Kt0[s] * Aa[s][i] - Kt1[s] * Bb[s][i];

            // T1 partial over own k-half (pair-packed), combine across h
            ull tp0 = 0ull, tp1 = 0ull, tp2 = 0ull, tp3 = 0ull;
#pragma unroll
            for (int kk = 0; kk < 4; ++kk) {
                const ull ck = ff_dup(cu[kk]);
                tp0 = ff_fma2(ck, Fpk[kk][0], tp0);
                tp1 = ff_fma2(ck, Fpk[kk][1], tp1);
                tp2 = ff_fma2(ck, Fpk[kk][2], tp2);
                tp3 = ff_fma2(ck, Fpk[kk][3], tp3);
            }
            tp0 = ff_add2(tp0, shflx8_64(tp0));
            tp1 = ff_add2(tp1, shflx8_64(tp1));
            tp2 = ff_add2(tp2, shflx8_64(tp2));
            tp3 = ff_add2(tp3, shflx8_64(tp3));
            {
                const ull sa = h ? tp2 : tp0;
                const ull sb = h ? tp3 : tp1;
                ulonglong2 st; st.x = sa; st.y = sb;
                *(ulonglong2*)&sT1[s][g * 72 + e * 8 + j0] = st;
            }
        }
        __syncwarp();

        // ================= PHASE 3 (both streams) =================
#pragma unroll
        for (int s = 0; s < 2; ++s) {
            const float4 Mh = *(const float4*)&sMu[s][g * 8 + j0];
            const float Mu[4] = {Mh.x, Mh.y, Mh.z, Mh.w};
            float mp = 0.f, nh0 = 0.f, nh1 = 0.f;
#pragma unroll
            for (int i = 0; i < 4; ++i) {
                mp  = fmaf(Frh[i],  Mu[i], mp);
                nh0 = fmaf(HF0h[i], Mu[i], nh0);
                nh1 = fmaf(HF1h[i], Mu[i], nh1);
            }
            mp  += __shfl_xor_sync(0xffffffffu, mp, 8);
            nh0 += __shfl_xor_sync(0xffffffffu, nh0, 8);
            nh1 += __shfl_xor_sync(0xffffffffu, nh1, 8);

            ull cp0 = Qp0, cp1 = Qp1;
#pragma unroll
            for (int k = 0; k < 8; ++k) {
                const ulonglong2 tv = *(const ulonglong2*)&sT1[s][g * 72 + k * 8 + j0];
                cp0 = ff_fma2(Fd[k], tv.x, cp0);
                cp1 = ff_fma2(Fd[k], tv.y, cp1);
            }
            {
                const float2 c0 = ff_unpack(cp0), c1 = ff_unpack(cp1);
                cov[s][0] = c0.x; cov[s][1] = c0.y; cov[s][2] = c1.x; cov[s][3] = c1.y;
            }
            mean_e[s] = mp;
            hm0[s] = nh0; hm1[s] = nh1;
            x[s] = xn[s];
        }
        // Race-freedom (per stream region, as in R4): sHP/sMu writes sit before
        // a __syncwarp that precedes their reads; sT1 reads (P3 of t) happen
        // before P2(t+1) writes, separated by the P1(t+1)->syncwarp barrier.
    }
}

extern "C" void kernel_launch(void* const* d_in, const int* in_sizes, int n_in,
                              void* d_out, int out_size)
{
    (void)in_sizes; (void)n_in; (void)out_size;
    const float* xin   = (const float*)d_in[0];
    const float* mean0 = (const float*)d_in[1];
    const float* cov0  = (const float*)d_in[2];
    const float* F     = (const float*)d_in[3];
    const float* H     = (const float*)d_in[4];
    const float* Q     = (const float*)d_in[5];
    const float* R     = (const float*)d_in[6];
    float* out = (float*)d_out;

    kf_kernel<<<SCAN_BLOCKS + FILL_BLOCKS, 32>>>(xin, mean0, cov0, F, H, Q, R, out);
}

// round 8
// speedup vs baseline: 2.0990x; 2.0990x over previous
#include <cuda_runtime.h>

#define KF_B 2048
#define KF_T 512
#define KF_D 8
#define KF_M 2

#define KF_TC 288   // scan steps with full Riccati; beyond this cov/K are converged

// Output layout (float offsets): means, covs, Rs, Hs concatenated.
#define OFF_MEANS 0
#define OFF_COVS  (KF_B * KF_T * KF_D)                       // 8388608
#define OFF_RS    (OFF_COVS + KF_B * KF_T * KF_D * KF_D)     // 75497472
#define OFF_HS    (OFF_RS + KF_B * KF_T * KF_M * KF_M)       // 79691776

#define SCAN_BLOCKS (KF_B / 2)   // 1024 blocks, 2 chains per 32-thread block
#define FILL_BLOCKS 256

typedef unsigned long long ull;

__device__ __forceinline__ ull ff_pack2(float lo, float hi) {
    ull r;
    asm("mov.b64 %0, {%1, %2};" : "=l"(r) : "f"(lo), "f"(hi));
    return r;
}
__device__ __forceinline__ ull ff_dup(float v) { return ff_pack2(v, v); }
__device__ __forceinline__ ull ff_fma2(ull a, ull b, ull c) {
    ull r;
    asm("fma.rn.f32x2 %0, %1, %2, %3;" : "=l"(r) : "l"(a), "l"(b), "l"(c));
    return r;
}
__device__ __forceinline__ ull ff_add2(ull a, ull b) {
    ull r;
    asm("add.rn.f32x2 %0, %1, %2;" : "=l"(r) : "l"(a), "l"(b));
    return r;
}
__device__ __forceinline__ float2 ff_unpack(ull v) {
    float2 r;
    asm("mov.b64 {%0, %1}, %2;" : "=f"(r.x), "=f"(r.y) : "l"(v));
    return r;
}
__device__ __forceinline__ ull shflx8_64(ull v) {
    float2 p = ff_unpack(v);
    p.x = __shfl_xor_sync(0xffffffffu, p.x, 8);
    p.y = __shfl_xor_sync(0xffffffffu, p.y, 8);
    return ff_pack2(p.x, p.y);
}

__global__ void __launch_bounds__(32) kf_kernel(
    const float* __restrict__ xin_g,   // [B,T,M]
    const float* __restrict__ mean0,   // [B,D]
    const float* __restrict__ cov0,    // [B,D,D]
    const float* __restrict__ Fg,      // [D,D]
    const float* __restrict__ Hg,      // [M,D]
    const float* __restrict__ Qg,      // [D,D]
    const float* __restrict__ Rg,      // [M,M]
    float* __restrict__ out)
{
    // ---------------- broadcast-fill blocks (Rs, Hs) ----------------
    if (blockIdx.x >= SCAN_BLOCKS) {
        const size_t BT = (size_t)KF_B * KF_T;
        float4 r4 = *(const float4*)Rg;
        float4 h0v = *(const float4*)(Hg + 0);
        float4 h1v = *(const float4*)(Hg + 4);
        float4 h2v = *(const float4*)(Hg + 8);
        float4 h3v = *(const float4*)(Hg + 12);
        float4* Rs = (float4*)(out + OFF_RS);
        float4* Hs = (float4*)(out + OFF_HS);
        const size_t nthr = (size_t)FILL_BLOCKS * 32;
        const size_t tid  = (size_t)(blockIdx.x - SCAN_BLOCKS) * 32 + threadIdx.x;
        for (size_t i = tid; i < BT; i += nthr)
            Rs[i] = r4;
        for (size_t i = tid; i < BT; i += nthr) {
            float4* p = Hs + i * 4;
            p[0] = h0v; p[1] = h1v; p[2] = h2v; p[3] = h3v;
        }
        return;
    }

    // ---------------- scan: 2 chains/warp, 16 lanes/chain ----------------
    // lane = g*16 + h*8 + e : chain g, half h (k/j range [4h,4h+4)), state row e
    const int lane = threadIdx.x & 31;
    const int g    = lane >> 4;
    const int sub  = lane & 15;
    const int e    = sub & 7;
    const int h    = sub >> 3;
    const int b    = blockIdx.x * 2 + g;
    const bool h0  = (h == 0);
    const int j0   = 4 * h;

    // ---- loop-invariant registers ----
    float H0h[4], H1h[4];              // H[m][j0+i]
#pragma unroll
    for (int i = 0; i < 4; ++i) { H0h[i] = Hg[j0 + i]; H1h[i] = Hg[8 + j0 + i]; }

    float Frow[8];                     // F[e][:]
#pragma unroll
    for (int j = 0; j < 8; ++j) Frow[j] = Fg[e * 8 + j];
    float Frh[4];                      // F[e][j0+i]
#pragma unroll
    for (int i = 0; i < 4; ++i) Frh[i] = Fg[e * 8 + j0 + i];

    // HF[m][j] for j in this half (lets hm = H*mean_p be tracked locally)
    float HF0h[4], HF1h[4];
#pragma unroll
    for (int i = 0; i < 4; ++i) {
        const int j = j0 + i;
        float a0 = 0.f, a1 = 0.f;
#pragma unroll
        for (int k = 0; k < 8; ++k) {
            a0 = fmaf(Hg[k],     Fg[k * 8 + j], a0);
            a1 = fmaf(Hg[8 + k], Fg[k * 8 + j], a1);
        }
        HF0h[i] = a0; HF1h[i] = a1;
    }

    // Fpk[kk][p] = (F[2p][j0+kk], F[2p+1][j0+kk])   (T1 partial operands)
    ull Fpk[4][4];
#pragma unroll
    for (int kk = 0; kk < 4; ++kk)
#pragma unroll
        for (int p = 0; p < 4; ++p)
            Fpk[kk][p] = ff_pack2(Fg[(2 * p) * 8 + j0 + kk], Fg[(2 * p + 1) * 8 + j0 + kk]);

    const ull Qp0 = ff_pack2(Qg[e * 8 + j0],     Qg[e * 8 + j0 + 1]);
    const ull Qp1 = ff_pack2(Qg[e * 8 + j0 + 2], Qg[e * 8 + j0 + 3]);

    const float r00 = Rg[0], r01 = Rg[1], r11 = Rg[3];

    // ---- per-chain state: half cov row, replicated mean/hm ----
    float cov[4];
    {
        float4 c = *(const float4*)(cov0 + b * 64 + e * 8 + j0);
        cov[0]=c.x; cov[1]=c.y; cov[2]=c.z; cov[3]=c.w;
    }
    float mean_e = mean0[b * 8 + e];
    float hm0, hm1;
    {
        float4 a = *(const float4*)(mean0 + b * 8);
        float4 c = *(const float4*)(mean0 + b * 8 + 4);
        float m[8] = {a.x,a.y,a.z,a.w,c.x,c.y,c.z,c.w};
        float s0 = 0.f, s1 = 0.f;
#pragma unroll
        for (int j = 0; j < 8; ++j) {
            s0 = fmaf(Hg[j],     m[j], s0);
            s1 = fmaf(Hg[8 + j], m[j], s1);
        }
        hm0 = s0; hm1 = s1;
    }

    float* outM = out + OFF_MEANS + (size_t)b * (KF_T * KF_D);
    float* outC = out + OFF_COVS  + (size_t)b * (KF_T * KF_D * KF_D);
    const float* xrow = xin_g + (size_t)b * (KF_T * KF_M);

    // SMEM exchange buffers (bank-conflict-free, verified per access pattern)
    __shared__ __align__(16) float sHP[2 * 16];   // [g]: hp0[0..7]@0, hp1[0..7]@8
    __shared__ __align__(16) float sMu[2 * 8];
    __shared__ __align__(16) float sT1[2 * 72];   // chain stride 72 floats
    __shared__ __align__(16) float sMuT[2][2 * 8];  // tail: double-buffered mean exchange

    float2 x = *(const float2*)xrow;   // prefetch t=0

    // ================= full Riccati scan: t < KF_TC =================
#pragma unroll 1
    for (int t = 0; t < KF_TC; ++t) {
        // emit state BEFORE consuming x_t (1-step-ahead semantics)
        if (h0) outM[t * 8 + e] = mean_e;
        *(float4*)(outC + t * 64 + e * 8 + j0) = make_float4(cov[0], cov[1], cov[2], cov[3]);

        const int tn = t + 1;                     // t+1 <= KF_TC < KF_T, safe
        const float2 xn = *(const float2*)(xrow + tn * 2);

        // HP[m][e] partial over this half of row e, then combine across h
        float hp0 = 0.f, hp1 = 0.f;
#pragma unroll
        for (int i = 0; i < 4; ++i) {
            hp0 = fmaf(H0h[i], cov[i], hp0);
            hp1 = fmaf(H1h[i], cov[i], hp1);
        }
        hp0 += __shfl_xor_sync(0xffffffffu, hp0, 8);
        hp1 += __shfl_xor_sync(0xffffffffu, hp1, 8);

        if (h0) { sHP[g * 16 + e] = hp0; sHP[g * 16 + 8 + e] = hp1; }
        __syncwarp();

        const float4 Ah = *(const float4*)&sHP[g * 16 + j0];       // hp0[j], j in half
        const float4 Bh = *(const float4*)&sHP[g * 16 + 8 + j0];   // hp1[j]
        const float Aa[4] = {Ah.x, Ah.y, Ah.z, Ah.w};
        const float Bb[4] = {Bh.x, Bh.y, Bh.z, Bh.w};

        // S partials over this half, combine across h
        float S00 = 0.f, S01 = 0.f, S11 = 0.f;
#pragma unroll
        for (int i = 0; i < 4; ++i) {
            S00 = fmaf(H0h[i], Aa[i], S00);
            S01 = fmaf(H1h[i], Aa[i], S01);
            S11 = fmaf(H1h[i], Bb[i], S11);
        }
        S00 = r00 + S00 + __shfl_xor_sync(0xffffffffu, S00, 8);
        S01 = r01 + S01 + __shfl_xor_sync(0xffffffffu, S01, 8);
        S11 = r11 + S11 + __shfl_xor_sync(0xffffffffu, S11, 8);

        const float idet = __fdividef(1.0f, fmaf(S00, S11, -S01 * S01));
        const float Kt0 = (S11 * hp0 - S01 * hp1) * idet;   // Kt[0][e]
        const float Kt1 = (S00 * hp1 - S01 * hp0) * idet;   // Kt[1][e]
        const float rs0 = x.x - hm0;
        const float rs1 = x.y - hm1;
        const float mu  = fmaf(Kt0, rs0, fmaf(Kt1, rs1, mean_e));   // mean_u[e]
        if (h0) sMu[g * 8 + e] = mu;

        // cov_u half-row
        float cu[4];
#pragma unroll
        for (int i = 0; i < 4; ++i)
            cu[i] = cov[i] - Kt0 * Aa[i] - Kt1 * Bb[i];

        // T1[e][:] partial over this lane's k-half (pair-packed), combine across h
        ull tp0 = 0ull, tp1 = 0ull, tp2 = 0ull, tp3 = 0ull;
#pragma unroll
        for (int kk = 0; kk < 4; ++kk) {
            const ull ck = ff_dup(cu[kk]);
            tp0 = ff_fma2(ck, Fpk[kk][0], tp0);
            tp1 = ff_fma2(ck, Fpk[kk][1], tp1);
            tp2 = ff_fma2(ck, Fpk[kk][2], tp2);
            tp3 = ff_fma2(ck, Fpk[kk][3], tp3);
        }
        tp0 = ff_add2(tp0, shflx8_64(tp0));
        tp1 = ff_add2(tp1, shflx8_64(tp1));
        tp2 = ff_add2(tp2, shflx8_64(tp2));
        tp3 = ff_add2(tp3, shflx8_64(tp3));
        {
            const ull sa = h ? tp2 : tp0;
            const ull sb = h ? tp3 : tp1;
            ulonglong2 st; st.x = sa; st.y = sb;
            *(ulonglong2*)&sT1[g * 72 + e * 8 + j0] = st;
        }
        __syncwarp();

        // mean_p / hm partials from mean_u, combine across h
        const float4 Mh = *(const float4*)&sMu[g * 8 + j0];
        const float Mu[4] = {Mh.x, Mh.y, Mh.z, Mh.w};
        float mp = 0.f, nh0 = 0.f, nh1 = 0.f;
#pragma unroll
        for (int i = 0; i < 4; ++i) {
            mp  = fmaf(Frh[i],  Mu[i], mp);
            nh0 = fmaf(HF0h[i], Mu[i], nh0);
            nh1 = fmaf(HF1h[i], Mu[i], nh1);
        }
        mp  += __shfl_xor_sync(0xffffffffu, mp, 8);
        nh0 += __shfl_xor_sync(0xffffffffu, nh0, 8);
        nh1 += __shfl_xor_sync(0xffffffffu, nh1, 8);

        // cov_p[e][half] = sum_k F[e][k] * T1[k][half] + Q[e][half]
        ull cp0 = Qp0, cp1 = Qp1;
#pragma unroll
        for (int k = 0; k < 8; ++k) {
            const ulonglong2 tv = *(const ulonglong2*)&sT1[g * 72 + k * 8 + j0];
            const ull fk = ff_dup(Frow[k]);
            cp0 = ff_fma2(fk, tv.x, cp0);
            cp1 = ff_fma2(fk, tv.y, cp1);
        }
        {
            const float2 c0 = ff_unpack(cp0), c1 = ff_unpack(cp1);
            cov[0] = c0.x; cov[1] = c0.y; cov[2] = c1.x; cov[3] = c1.y;
        }
        mean_e = mp;
        hm0 = nh0; hm1 = nh1;
        x = xn;
    }

    // ================= epilogue: frozen gain from converged cov =================
    // Compute K_Tc from P_Tc, then u = F*K and G-half-row = F[e][half] - u0*H0 - u1*H1.
    float u0e, u1e, G4[4];
    {
        __syncwarp();
        float hp0 = 0.f, hp1 = 0.f;
#pragma unroll
        for (int i = 0; i < 4; ++i) {
            hp0 = fmaf(H0h[i], cov[i], hp0);
            hp1 = fmaf(H1h[i], cov[i], hp1);
        }
        hp0 += __shfl_xor_sync(0xffffffffu, hp0, 8);
        hp1 += __shfl_xor_sync(0xffffffffu, hp1, 8);
        if (h0) { sHP[g * 16 + e] = hp0; sHP[g * 16 + 8 + e] = hp1; }
        __syncwarp();

        // Full hp rows (broadcast LDS)
        const float4 A0 = *(const float4*)&sHP[g * 16 + 0];
        const float4 A1 = *(const float4*)&sHP[g * 16 + 4];
        const float4 B0 = *(const float4*)&sHP[g * 16 + 8];
        const float4 B1 = *(const float4*)&sHP[g * 16 + 12];
        const float Af[8] = {A0.x,A0.y,A0.z,A0.w,A1.x,A1.y,A1.z,A1.w};
        const float Bf[8] = {B0.x,B0.y,B0.z,B0.w,B1.x,B1.y,B1.z,B1.w};

        float S00 = r00, S01 = r01, S11 = r11, a0 = 0.f, a1 = 0.f;
#pragma unroll
        for (int j = 0; j < 8; ++j) {
            S00 = fmaf(Hg[j],     Af[j], S00);
            S01 = fmaf(Hg[8 + j], Af[j], S01);
            S11 = fmaf(Hg[8 + j], Bf[j], S11);
            a0  = fmaf(Frow[j],   Af[j], a0);    // (F hp0)[e]
            a1  = fmaf(Frow[j],   Bf[j], a1);
        }
        const float idet = __fdividef(1.0f, fmaf(S00, S11, -S01 * S01));
        u0e = (S11 * a0 - S01 * a1) * idet;      // (F K0)[e]
        u1e = (S00 * a1 - S01 * a0) * idet;      // (F K1)[e]
#pragma unroll
        for (int i = 0; i < 4; ++i)
            G4[i] = Frh[i] - u0e * H0h[i] - u1e * H1h[i];
    }

    // ================= cheap tail: t in [KF_TC, KF_T) =================
    // covs are converged (emit the register copy); means follow
    //   mean' = G*mean + u0*x0 + u1*x1  (constant coefficients).
    const float4 covOut = make_float4(cov[0], cov[1], cov[2], cov[3]);
#pragma unroll 1
    for (int t = KF_TC; t < KF_T; ++t) {
        const int pb = t & 1;

        if (h0) outM[t * 8 + e] = mean_e;
        *(float4*)(outC + t * 64 + e * 8 + j0) = covOut;

        const int tn = (t + 1 < KF_T) ? t + 1 : t;
        const float2 xn = *(const float2*)(xrow + tn * 2);

        if (h0) sMuT[pb][g * 8 + e] = mean_e;
        __syncwarp();
        const float4 Mh = *(const float4*)&sMuT[pb][g * 8 + j0];
        float pm = G4[0] * Mh.x;
        pm = fmaf(G4[1], Mh.y, pm);
        pm = fmaf(G4[2], Mh.z, pm);
        pm = fmaf(G4[3], Mh.w, pm);
        pm += __shfl_xor_sync(0xffffffffu, pm, 8);
        mean_e = fmaf(u0e, x.x, fmaf(u1e, x.y, pm));
        x = xn;
        // Double-buffered sMuT: next iteration writes the other buffer, so this
        // iteration's reads can't be overwritten early.
    }
}

extern "C" void kernel_launch(void* const* d_in, const int* in_sizes, int n_in,
                              void* d_out, int out_size)
{
    (void)in_sizes; (void)n_in; (void)out_size;
    const float* xin   = (const float*)d_in[0];
    const float* mean0 = (const float*)d_in[1];
    const float* cov0  = (const float*)d_in[2];
    const float* F     = (const float*)d_in[3];
    const float* H     = (const float*)d_in[4];
    const float* Q     = (const float*)d_in[5];
    const float* R     = (const float*)d_in[6];
    float* out = (float*)d_out;

    kf_kernel<<<SCAN_BLOCKS + FILL_BLOCKS, 32>>>(xin, mean0, cov0, F, H, Q, R, out);
}